// round 12
// baseline (speedup 1.0000x reference)
#include <cuda_runtime.h>
#include <cstdint>

#define IN_CHAN 4096
#define BATCH   16
#define NTOT    (3 * IN_CHAN)          // 12288 stacked W rows (q,k,v)
#define KSPLIT  32
#define KS_LEN  (IN_CHAN / KSPLIT)     // 128 k per block
#define ROWS_PB 128                    // W rows per block (4 warps x 32)
#define NNODES  32
#define NCHUNK  16
#define CHLEN   (IN_CHAN / NCHUNK)     // 256
#define QHALF   4.0f
#define LOG2E   1.4426950408889634f
#define PI_F    3.14159265358979323846f

#define XW      68                     // x smem row pitch in b32 words (KS_LEN/2 + pad)

// Scratch (device globals; no allocation allowed anywhere)
__device__ float g_part[KSPLIT * NTOT * BATCH];       // split-K partials (25MB, L2-resident)
__device__ float g_nodes[BATCH][NCHUNK][2][NNODES];   // per j-chunk partial F,G

__device__ __forceinline__ float ex2(float x) {
    float r;
    asm("ex2.approx.ftz.f32 %0, %1;" : "=f"(r) : "f"(x));
    return r;
}
// pack two fp32 into bf16x2 (consistent convention for A and B fragments)
__device__ __forceinline__ uint32_t packbf(float hi_elem, float lo_elem) {
    uint32_t r;
    asm("cvt.rn.bf16x2.f32 %0, %1, %2;" : "=r"(r) : "f"(hi_elem), "f"(lo_elem));
    return r;
}
// split a float2 (k, k+1 adjacent) into bf16x2 hi and lo parts
__device__ __forceinline__ void split2(float2 f, uint32_t& hi, uint32_t& lo) {
    hi = packbf(f.y, f.x);
    float f0h = __uint_as_float(hi << 16);
    float f1h = __uint_as_float(hi & 0xffff0000u);
    lo = packbf(f.y - f1h, f.x - f0h);
}
// m16n8k16 bf16 MMA, fp32 accumulate
__device__ __forceinline__ void mma16816(float* d, const uint32_t* a,
                                         uint32_t b0, uint32_t b1) {
    asm volatile(
        "mma.sync.aligned.m16n8k16.row.col.f32.bf16.bf16.f32 "
        "{%0,%1,%2,%3}, {%4,%5,%6,%7}, {%8,%9}, {%0,%1,%2,%3};"
        : "+f"(d[0]), "+f"(d[1]), "+f"(d[2]), "+f"(d[3])
        : "r"(a[0]), "r"(a[1]), "r"(a[2]), "r"(a[3]), "r"(b0), "r"(b1));
}

// ---------------------------------------------------------------------------
// Kernel 1: QKV GEMM on tensor cores (bf16x3 split), split-K, prefetched,
// wave-balanced.  KSPLIT=32 -> grid 3072 on 1036 CTA slots (7 CTAs/SM via
// launch_bounds) = 2.97 waves, eff 0.99 (was 1.48 waves, 0.74).
// Block 128 thr = 4 warps x 32 rows x 16 batches x 128 k.  A fragments
// LDG.64 direct from global, prefetched one k16 step ahead; x converted
// once to padded smem bf16 (hi & lo); B-fragment LDS.32 conflict-free.
// ---------------------------------------------------------------------------
__global__ __launch_bounds__(128, 7) void qkv_gemm_kernel(
    const float* __restrict__ x,
    const float* __restrict__ wq,
    const float* __restrict__ wk,
    const float* __restrict__ wv)
{
    __shared__ uint32_t xhi[BATCH * XW];   // [n][k/2] bf16 pairs, padded
    __shared__ uint32_t xlo[BATCH * XW];

    const int tid  = threadIdx.x;
    const int wid  = tid >> 5;
    const int lane = tid & 31;

    const int gn0 = blockIdx.x * ROWS_PB;
    const int mat = gn0 >> 12;
    const int n0  = gn0 & (IN_CHAN - 1);
    const int kb  = blockIdx.y * KS_LEN;
    const float* w = (mat == 0) ? wq : (mat == 1) ? wk : wv;

    // ---- stage x slice as bf16 hi/lo: 16 b x (KS_LEN/2=64) float2 ----
#pragma unroll
    for (int i = 0; i < 8; ++i) {
        int idx = tid + i * 128;        // [0,1024)
        int b   = idx >> 6;
        int kw  = idx & 63;             // float2 index within row
        float2 f = *(const float2*)(x + (size_t)b * IN_CHAN + kb + kw * 2);
        uint32_t h, l;
        split2(f, h, l);
        xhi[b * XW + kw] = h;
        xlo[b * XW + kw] = l;
    }
    __syncthreads();

    // warp owns rows m0..m0+31 (2 m-tiles of 16)
    const int m0   = n0 + wid * 32;
    const int la4  = lane >> 2;         // 0..7
    const int c0   = (lane & 3) * 2;    // col pair base within k16
    const float* p00 = w + (size_t)(m0 + la4)      * IN_CHAN + kb + c0;
    const float* p01 = w + (size_t)(m0 + la4 + 8)  * IN_CHAN + kb + c0;
    const float* p10 = w + (size_t)(m0 + 16 + la4) * IN_CHAN + kb + c0;
    const float* p11 = w + (size_t)(m0 + 24 + la4) * IN_CHAN + kb + c0;

    float d[2][2][4];                   // [m-tile][n-tile][4]
#pragma unroll
    for (int t = 0; t < 2; ++t)
#pragma unroll
        for (int n = 0; n < 2; ++n)
#pragma unroll
            for (int j = 0; j < 4; ++j) d[t][n][j] = 0.f;

    const int brow0 = (lane >> 2) * XW;        // n-tile 0 row base
    const int brow1 = (8 + (lane >> 2)) * XW;  // n-tile 1

    // software prefetch registers (depth 1, 8 float2)
    float2 pf[8];
#define PF_LOAD(kk)                                   \
    do {                                              \
        pf[0] = *(const float2*)(p00 + (kk));         \
        pf[1] = *(const float2*)(p01 + (kk));         \
        pf[2] = *(const float2*)(p00 + (kk) + 8);     \
        pf[3] = *(const float2*)(p01 + (kk) + 8);     \
        pf[4] = *(const float2*)(p10 + (kk));         \
        pf[5] = *(const float2*)(p11 + (kk));         \
        pf[6] = *(const float2*)(p10 + (kk) + 8);     \
        pf[7] = *(const float2*)(p11 + (kk) + 8);     \
    } while (0)

    PF_LOAD(0);

#pragma unroll 4
    for (int k = 0; k < KS_LEN; k += 16) {
        float2 cur[8];
#pragma unroll
        for (int i = 0; i < 8; ++i) cur[i] = pf[i];
        if (k + 16 < KS_LEN) PF_LOAD(k + 16);

        uint32_t ah[2][4], al[2][4];
        split2(cur[0], ah[0][0], al[0][0]);
        split2(cur[1], ah[0][1], al[0][1]);
        split2(cur[2], ah[0][2], al[0][2]);
        split2(cur[3], ah[0][3], al[0][3]);
        split2(cur[4], ah[1][0], al[1][0]);
        split2(cur[5], ah[1][1], al[1][1]);
        split2(cur[6], ah[1][2], al[1][2]);
        split2(cur[7], ah[1][3], al[1][3]);

        // B fragments: word index k/2 + (lane&3), +4 for the k+8 half
        const int kw = (k >> 1) + (lane & 3);
        uint32_t b0h0 = xhi[brow0 + kw],     b1h0 = xhi[brow0 + kw + 4];
        uint32_t b0l0 = xlo[brow0 + kw],     b1l0 = xlo[brow0 + kw + 4];
        uint32_t b0h1 = xhi[brow1 + kw],     b1h1 = xhi[brow1 + kw + 4];
        uint32_t b0l1 = xlo[brow1 + kw],     b1l1 = xlo[brow1 + kw + 4];

#pragma unroll
        for (int t = 0; t < 2; ++t) {
            mma16816(d[t][0], ah[t], b0h0, b1h0);   // hi*hi
            mma16816(d[t][0], ah[t], b0l0, b1l0);   // hi*lo
            mma16816(d[t][0], al[t], b0h0, b1h0);   // lo*hi
            mma16816(d[t][1], ah[t], b0h1, b1h1);
            mma16816(d[t][1], ah[t], b0l1, b1l1);
            mma16816(d[t][1], al[t], b0h1, b1h1);
        }
    }
#undef PF_LOAD

    // epilogue: d[..][0,1]: row la4, batches c0,c0+1; d[..][2,3]: row la4+8
    const int p = blockIdx.y;
#pragma unroll
    for (int t = 0; t < 2; ++t) {
#pragma unroll
        for (int n = 0; n < 2; ++n) {
            int gnA = gn0 + wid * 32 + t * 16 + la4;
            int bcol = n * 8 + c0;
            float* dstA = g_part + ((size_t)p * NTOT + gnA) * BATCH + bcol;
            *(float2*)dstA = make_float2(d[t][n][0], d[t][n][1]);
            float* dstB = g_part + ((size_t)p * NTOT + gnA + 8) * BATCH + bcol;
            *(float2*)dstB = make_float2(d[t][n][2], d[t][n][3]);
        }
    }
}

// ---------------------------------------------------------------------------
// Kernel 2: nodes. Reduces its own k,v chunk from g_part inline (+bias),
// then evaluates F,G partials at 32 fixed Chebyshev nodes (domain +-QHALF).
// grid (16 batches, 16 chunks) x 512 thr.
// ---------------------------------------------------------------------------
__global__ __launch_bounds__(512) void attn_nodes_kernel(
    const float* __restrict__ bk,
    const float* __restrict__ bv)
{
    __shared__ float ks[CHLEN], vs[CHLEN];
    const int b   = blockIdx.x;
    const int ch  = blockIdx.y;
    const int tid = threadIdx.x;

    {
        int n   = tid & (CHLEN - 1);
        int sel = tid >> 8;             // 0 = k (mat 1), 1 = v (mat 2)
        int gn  = (1 + sel) * IN_CHAN + ch * CHLEN + n;
        float s = 0.f;
#pragma unroll
        for (int p = 0; p < KSPLIT; ++p)
            s += g_part[((size_t)p * NTOT + gn) * BATCH + b];
        s += (sel ? bv : bk)[ch * CHLEN + n];
        if (sel) vs[n] = s;
        else     ks[n] = s;
    }
    __syncthreads();

    const int node = tid >> 4;
    const int sub  = tid & 15;

    const float xt = QHALF * cosf(PI_F * (node + 0.5f) / NNODES);
    const float a  = xt * LOG2E;

    float aF = 0.f, aG = 0.f;
#pragma unroll
    for (int j = sub; j < CHLEN; j += 16) {
        float e = ex2(a * ks[j]);
        aG += e;
        aF = fmaf(e, vs[j], aF);
    }
#pragma unroll
    for (int o = 8; o; o >>= 1) {
        aF += __shfl_xor_sync(0xffffffffu, aF, o);
        aG += __shfl_xor_sync(0xffffffffu, aG, o);
    }
    if (sub == 0) {
        g_nodes[b][ch][0][node] = aF;
        g_nodes[b][ch][1][node] = aG;
    }
}

// ---------------------------------------------------------------------------
// Kernel 3: fused fit + eval. Sum node chunks, 32x32 DCT -> Chebyshev
// coeffs, inline split-K reduce of q (+bq), Clenshaw -> out.
// grid (32 x-chunks, 16 batches) x 128 thr.
// ---------------------------------------------------------------------------
__global__ __launch_bounds__(128) void attn_eval_kernel(
    const float* __restrict__ bq,
    float* __restrict__ out)
{
    __shared__ float Fv[NNODES], Gv[NNODES], tab[128], cF[NNODES], cG[NNODES];
    const int b   = blockIdx.y;
    const int tid = threadIdx.x;

    if (tid < 64) {
        int node = tid & 31;
        int sel  = tid >> 5;
        float v = 0.f;
#pragma unroll
        for (int ch = 0; ch < NCHUNK; ++ch)
            v += g_nodes[b][ch][sel][node];
        if (sel == 0) Fv[node] = v;
        else          Gv[node] = v;
    }
    tab[tid] = cosf((PI_F / 64.0f) * (float)tid);
    __syncthreads();

    if (tid < 64) {
        int m = tid & 31;
        const float* src = (tid < 32) ? Fv : Gv;
        float c = 0.f;
#pragma unroll
        for (int t = 0; t < NNODES; ++t)
            c = fmaf(src[t], tab[(m * (2 * t + 1)) & 127], c);
        c *= 2.0f / NNODES;
        if (tid < 32) cF[m] = c;
        else          cG[m] = c;
    }

    const int i = blockIdx.x * 128 + tid;
    float q = 0.f;
#pragma unroll
    for (int p = 0; p < KSPLIT; ++p)
        q += g_part[((size_t)p * NTOT + i) * BATCH + b];
    q += bq[i];

    __syncthreads();

    float y = q * (1.0f / QHALF);
    y = fminf(1.f, fmaxf(-1.f, y));
    const float y2 = 2.f * y;

    float f1 = 0.f, f2 = 0.f, g1 = 0.f, g2 = 0.f;
#pragma unroll
    for (int m = NNODES - 1; m >= 1; --m) {
        float tf = fmaf(y2, f1, cF[m] - f2);
        f2 = f1; f1 = tf;
        float tg = fmaf(y2, g1, cG[m] - g2);
        g2 = g1; g1 = tg;
    }
    float F = fmaf(y, f1, 0.5f * cF[0]) - f2;
    float G = fmaf(y, g1, 0.5f * cG[0]) - g2;

    out[(size_t)b * IN_CHAN + i] = F / G;
}

// ---------------------------------------------------------------------------
extern "C" void kernel_launch(void* const* d_in, const int* in_sizes, int n_in,
                              void* d_out, int out_size)
{
    (void)in_sizes; (void)n_in; (void)out_size;
    const float* x  = (const float*)d_in[0];
    const float* wq = (const float*)d_in[1];
    const float* bq = (const float*)d_in[2];
    const float* wk = (const float*)d_in[3];
    const float* bk = (const float*)d_in[4];
    const float* wv = (const float*)d_in[5];
    const float* bv = (const float*)d_in[6];
    float* out = (float*)d_out;

    qkv_gemm_kernel<<<dim3(NTOT / ROWS_PB, KSPLIT), 128>>>(x, wq, wk, wv);
    attn_nodes_kernel<<<dim3(BATCH, NCHUNK), 512>>>(bk, bv);
    attn_eval_kernel<<<dim3(IN_CHAN / 128, BATCH), 128>>>(bq, out);
}

// round 13
// speedup vs baseline: 1.1504x; 1.1504x over previous
#include <cuda_runtime.h>
#include <cstdint>

#define IN_CHAN 4096
#define BATCH   16
#define NTOT    (3 * IN_CHAN)          // 12288 stacked W rows (q,k,v)
#define KSPLIT  32
#define KS_LEN  (IN_CHAN / KSPLIT)     // 128 k per block
#define ROWS_PB 128                    // W rows per block (4 warps x 32)
#define NNODES  32
#define NCHUNK  16
#define CHLEN   (IN_CHAN / NCHUNK)     // 256
#define QHALF   4.0f
#define LOG2E   1.4426950408889634f
#define PI_F    3.14159265358979323846f

#define XW      68                     // x smem row pitch in b32 words

// Scratch (device globals; no allocation allowed anywhere)
__device__ float g_part[KSPLIT * NTOT * BATCH];       // split-K partials (25MB)
__device__ float g_qkv[3 * BATCH * IN_CHAN];          // reduced q,k,v (b-major)
__device__ float g_nodes[BATCH][NCHUNK][2][NNODES];   // per j-chunk partial F,G

__device__ __forceinline__ float ex2(float x) {
    float r;
    asm("ex2.approx.ftz.f32 %0, %1;" : "=f"(r) : "f"(x));
    return r;
}
// pack two fp32 into bf16x2 (consistent convention for A and B fragments)
__device__ __forceinline__ uint32_t packbf(float hi_elem, float lo_elem) {
    uint32_t r;
    asm("cvt.rn.bf16x2.f32 %0, %1, %2;" : "=r"(r) : "f"(hi_elem), "f"(lo_elem));
    return r;
}
// split a float2 (k, k+1 adjacent) into bf16x2 hi and lo parts
__device__ __forceinline__ void split2(float2 f, uint32_t& hi, uint32_t& lo) {
    hi = packbf(f.y, f.x);
    float f0h = __uint_as_float(hi << 16);
    float f1h = __uint_as_float(hi & 0xffff0000u);
    lo = packbf(f.y - f1h, f.x - f0h);
}
// m16n8k16 bf16 MMA, fp32 accumulate
__device__ __forceinline__ void mma16816(float* d, const uint32_t* a,
                                         uint32_t b0, uint32_t b1) {
    asm volatile(
        "mma.sync.aligned.m16n8k16.row.col.f32.bf16.bf16.f32 "
        "{%0,%1,%2,%3}, {%4,%5,%6,%7}, {%8,%9}, {%0,%1,%2,%3};"
        : "+f"(d[0]), "+f"(d[1]), "+f"(d[2]), "+f"(d[3])
        : "r"(a[0]), "r"(a[1]), "r"(a[2]), "r"(a[3]), "r"(b0), "r"(b1));
}

// ---------------------------------------------------------------------------
// Kernel 1: QKV GEMM on tensor cores (bf16x3 split), split-K, prefetched,
// wave-balanced (unchanged from R12: 41.3us, DRAM 66%).
// ---------------------------------------------------------------------------
__global__ __launch_bounds__(128, 7) void qkv_gemm_kernel(
    const float* __restrict__ x,
    const float* __restrict__ wq,
    const float* __restrict__ wk,
    const float* __restrict__ wv)
{
    __shared__ uint32_t xhi[BATCH * XW];   // [n][k/2] bf16 pairs, padded
    __shared__ uint32_t xlo[BATCH * XW];

    const int tid  = threadIdx.x;
    const int wid  = tid >> 5;
    const int lane = tid & 31;

    const int gn0 = blockIdx.x * ROWS_PB;
    const int mat = gn0 >> 12;
    const int n0  = gn0 & (IN_CHAN - 1);
    const int kb  = blockIdx.y * KS_LEN;
    const float* w = (mat == 0) ? wq : (mat == 1) ? wk : wv;

    // ---- stage x slice as bf16 hi/lo: 16 b x (KS_LEN/2=64) float2 ----
#pragma unroll
    for (int i = 0; i < 8; ++i) {
        int idx = tid + i * 128;        // [0,1024)
        int b   = idx >> 6;
        int kw  = idx & 63;
        float2 f = *(const float2*)(x + (size_t)b * IN_CHAN + kb + kw * 2);
        uint32_t h, l;
        split2(f, h, l);
        xhi[b * XW + kw] = h;
        xlo[b * XW + kw] = l;
    }
    __syncthreads();

    const int m0   = n0 + wid * 32;
    const int la4  = lane >> 2;
    const int c0   = (lane & 3) * 2;
    const float* p00 = w + (size_t)(m0 + la4)      * IN_CHAN + kb + c0;
    const float* p01 = w + (size_t)(m0 + la4 + 8)  * IN_CHAN + kb + c0;
    const float* p10 = w + (size_t)(m0 + 16 + la4) * IN_CHAN + kb + c0;
    const float* p11 = w + (size_t)(m0 + 24 + la4) * IN_CHAN + kb + c0;

    float d[2][2][4];
#pragma unroll
    for (int t = 0; t < 2; ++t)
#pragma unroll
        for (int n = 0; n < 2; ++n)
#pragma unroll
            for (int j = 0; j < 4; ++j) d[t][n][j] = 0.f;

    const int brow0 = (lane >> 2) * XW;
    const int brow1 = (8 + (lane >> 2)) * XW;

    float2 pf[8];
#define PF_LOAD(kk)                                   \
    do {                                              \
        pf[0] = *(const float2*)(p00 + (kk));         \
        pf[1] = *(const float2*)(p01 + (kk));         \
        pf[2] = *(const float2*)(p00 + (kk) + 8);     \
        pf[3] = *(const float2*)(p01 + (kk) + 8);     \
        pf[4] = *(const float2*)(p10 + (kk));         \
        pf[5] = *(const float2*)(p11 + (kk));         \
        pf[6] = *(const float2*)(p10 + (kk) + 8);     \
        pf[7] = *(const float2*)(p11 + (kk) + 8);     \
    } while (0)

    PF_LOAD(0);

#pragma unroll 4
    for (int k = 0; k < KS_LEN; k += 16) {
        float2 cur[8];
#pragma unroll
        for (int i = 0; i < 8; ++i) cur[i] = pf[i];
        if (k + 16 < KS_LEN) PF_LOAD(k + 16);

        uint32_t ah[2][4], al[2][4];
        split2(cur[0], ah[0][0], al[0][0]);
        split2(cur[1], ah[0][1], al[0][1]);
        split2(cur[2], ah[0][2], al[0][2]);
        split2(cur[3], ah[0][3], al[0][3]);
        split2(cur[4], ah[1][0], al[1][0]);
        split2(cur[5], ah[1][1], al[1][1]);
        split2(cur[6], ah[1][2], al[1][2]);
        split2(cur[7], ah[1][3], al[1][3]);

        const int kw = (k >> 1) + (lane & 3);
        uint32_t b0h0 = xhi[brow0 + kw],     b1h0 = xhi[brow0 + kw + 4];
        uint32_t b0l0 = xlo[brow0 + kw],     b1l0 = xlo[brow0 + kw + 4];
        uint32_t b0h1 = xhi[brow1 + kw],     b1h1 = xhi[brow1 + kw + 4];
        uint32_t b0l1 = xlo[brow1 + kw],     b1l1 = xlo[brow1 + kw + 4];

#pragma unroll
        for (int t = 0; t < 2; ++t) {
            mma16816(d[t][0], ah[t], b0h0, b1h0);   // hi*hi
            mma16816(d[t][0], ah[t], b0l0, b1l0);   // hi*lo
            mma16816(d[t][0], al[t], b0h0, b1h0);   // lo*hi
            mma16816(d[t][1], ah[t], b0h1, b1h1);
            mma16816(d[t][1], ah[t], b0l1, b1l1);
            mma16816(d[t][1], al[t], b0h1, b1h1);
        }
    }
#undef PF_LOAD

    const int p = blockIdx.y;
#pragma unroll
    for (int t = 0; t < 2; ++t) {
#pragma unroll
        for (int n = 0; n < 2; ++n) {
            int gnA = gn0 + wid * 32 + t * 16 + la4;
            int bcol = n * 8 + c0;
            float* dstA = g_part + ((size_t)p * NTOT + gnA) * BATCH + bcol;
            *(float2*)dstA = make_float2(d[t][n][0], d[t][n][1]);
            float* dstB = g_part + ((size_t)p * NTOT + gnA + 8) * BATCH + bcol;
            *(float2*)dstB = make_float2(d[t][n][2], d[t][n][3]);
        }
    }
}

// ---------------------------------------------------------------------------
// Kernel 2: coalesced split-K reduce + bias -> g_qkv[mat][b][n] (b-major).
// Thread idx = gn*BATCH+b (consecutive) -> per p-step the warp reads 128B
// CONTIGUOUS (g_part[p*NTOT*BATCH + idx]); 32 steps unrolled for MLP.
// 25MB coalesced reads @ ~5-6TB/s ~= 4-5us.
// ---------------------------------------------------------------------------
__global__ __launch_bounds__(256) void reduce_bias_kernel(
    const float* __restrict__ bq,
    const float* __restrict__ bk,
    const float* __restrict__ bv)
{
    const int idx = blockIdx.x * 256 + threadIdx.x;   // [0, NTOT*BATCH)
    const int b   = idx & (BATCH - 1);
    const int gn  = idx >> 4;
    const int mat = gn >> 12;
    const int n   = gn & (IN_CHAN - 1);

    float s = 0.f;
#pragma unroll 8
    for (int p = 0; p < KSPLIT; ++p)
        s += g_part[(size_t)p * NTOT * BATCH + idx];

    const float* bias = (mat == 0) ? bq : (mat == 1) ? bk : bv;
    g_qkv[((size_t)mat * BATCH + b) * IN_CHAN + n] = s + bias[n];
}

// ---------------------------------------------------------------------------
// Kernel 3: nodes.  Loads its k,v chunk from g_qkv (contiguous, L2), then
// evaluates F,G partials at 32 fixed Chebyshev nodes (domain +-QHALF).
// grid (16 batches, 16 chunks) x 512 thr.
// ---------------------------------------------------------------------------
__global__ __launch_bounds__(512) void attn_nodes_kernel()
{
    __shared__ float ks[CHLEN], vs[CHLEN];
    const int b   = blockIdx.x;
    const int ch  = blockIdx.y;
    const int tid = threadIdx.x;

    {
        int n   = tid & (CHLEN - 1);
        int sel = tid >> 8;             // 0 = k (mat 1), 1 = v (mat 2)
        float s = g_qkv[((size_t)(1 + sel) * BATCH + b) * IN_CHAN + ch * CHLEN + n];
        if (sel) vs[n] = s;
        else     ks[n] = s;
    }
    __syncthreads();

    const int node = tid >> 4;
    const int sub  = tid & 15;

    const float xt = QHALF * cosf(PI_F * (node + 0.5f) / NNODES);
    const float a  = xt * LOG2E;

    float aF = 0.f, aG = 0.f;
#pragma unroll
    for (int j = sub; j < CHLEN; j += 16) {
        float e = ex2(a * ks[j]);
        aG += e;
        aF = fmaf(e, vs[j], aF);
    }
#pragma unroll
    for (int o = 8; o; o >>= 1) {
        aF += __shfl_xor_sync(0xffffffffu, aF, o);
        aG += __shfl_xor_sync(0xffffffffu, aG, o);
    }
    if (sub == 0) {
        g_nodes[b][ch][0][node] = aF;
        g_nodes[b][ch][1][node] = aG;
    }
}

// ---------------------------------------------------------------------------
// Kernel 4: fused fit + eval. Sum node chunks, 32x32 DCT -> Chebyshev
// coeffs, read q from g_qkv, Clenshaw -> out.
// grid (32 x-chunks, 16 batches) x 128 thr.
// ---------------------------------------------------------------------------
__global__ __launch_bounds__(128) void attn_eval_kernel(float* __restrict__ out)
{
    __shared__ float Fv[NNODES], Gv[NNODES], tab[128], cF[NNODES], cG[NNODES];
    const int b   = blockIdx.y;
    const int tid = threadIdx.x;

    if (tid < 64) {
        int node = tid & 31;
        int sel  = tid >> 5;
        float v = 0.f;
#pragma unroll
        for (int ch = 0; ch < NCHUNK; ++ch)
            v += g_nodes[b][ch][sel][node];
        if (sel == 0) Fv[node] = v;
        else          Gv[node] = v;
    }
    tab[tid] = cosf((PI_F / 64.0f) * (float)tid);
    __syncthreads();

    if (tid < 64) {
        int m = tid & 31;
        const float* src = (tid < 32) ? Fv : Gv;
        float c = 0.f;
#pragma unroll
        for (int t = 0; t < NNODES; ++t)
            c = fmaf(src[t], tab[(m * (2 * t + 1)) & 127], c);
        c *= 2.0f / NNODES;
        if (tid < 32) cF[m] = c;
        else          cG[m] = c;
    }

    const int i = blockIdx.x * 128 + tid;
    float q = g_qkv[(size_t)b * IN_CHAN + i];   // mat 0 = q

    __syncthreads();

    float y = q * (1.0f / QHALF);
    y = fminf(1.f, fmaxf(-1.f, y));
    const float y2 = 2.f * y;

    float f1 = 0.f, f2 = 0.f, g1 = 0.f, g2 = 0.f;
#pragma unroll
    for (int m = NNODES - 1; m >= 1; --m) {
        float tf = fmaf(y2, f1, cF[m] - f2);
        f2 = f1; f1 = tf;
        float tg = fmaf(y2, g1, cG[m] - g2);
        g2 = g1; g1 = tg;
    }
    float F = fmaf(y, f1, 0.5f * cF[0]) - f2;
    float G = fmaf(y, g1, 0.5f * cG[0]) - g2;

    out[(size_t)b * IN_CHAN + i] = F / G;
}

// ---------------------------------------------------------------------------
extern "C" void kernel_launch(void* const* d_in, const int* in_sizes, int n_in,
                              void* d_out, int out_size)
{
    (void)in_sizes; (void)n_in; (void)out_size;
    const float* x  = (const float*)d_in[0];
    const float* wq = (const float*)d_in[1];
    const float* bq = (const float*)d_in[2];
    const float* wk = (const float*)d_in[3];
    const float* bk = (const float*)d_in[4];
    const float* wv = (const float*)d_in[5];
    const float* bv = (const float*)d_in[6];
    float* out = (float*)d_out;

    qkv_gemm_kernel<<<dim3(NTOT / ROWS_PB, KSPLIT), 128>>>(x, wq, wk, wv);
    reduce_bias_kernel<<<(NTOT * BATCH) / 256, 256>>>(bq, bk, bv);
    attn_nodes_kernel<<<dim3(BATCH, NCHUNK), 512>>>();
    attn_eval_kernel<<<dim3(IN_CHAN / 128, BATCH), 128>>>(out);
}

// round 14
// speedup vs baseline: 1.1565x; 1.0054x over previous
#include <cuda_runtime.h>
#include <cstdint>

#define IN_CHAN 4096
#define BATCH   16
#define NTOT    (3 * IN_CHAN)          // 12288 stacked W rows (q,k,v)
#define KSPLIT  32
#define KS_LEN  (IN_CHAN / KSPLIT)     // 128 k per block
#define ROWS_PB 128                    // W rows per block (4 warps x 32)
#define NNODES  32
#define NCHUNK  16
#define CHLEN   (IN_CHAN / NCHUNK)     // 256
#define QHALF   4.0f
#define LOG2E   1.4426950408889634f
#define PI_F    3.14159265358979323846f

#define XW      68                     // x smem row pitch in b32 words (even!)

// Scratch (device globals; no allocation allowed anywhere)
__device__ float g_part[KSPLIT * NTOT * BATCH];       // split-K partials (25MB)
__device__ float g_qkv[3 * BATCH * IN_CHAN];          // reduced q,k,v (b-major)
__device__ float g_nodes[BATCH][NCHUNK][2][NNODES];   // per j-chunk partial F,G
__device__ float g_cheb[BATCH][2 * NNODES];           // Chebyshev coeffs F,G

__device__ __forceinline__ float ex2(float x) {
    float r;
    asm("ex2.approx.ftz.f32 %0, %1;" : "=f"(r) : "f"(x));
    return r;
}
__device__ __forceinline__ uint32_t packbf(float hi_elem, float lo_elem) {
    uint32_t r;
    asm("cvt.rn.bf16x2.f32 %0, %1, %2;" : "=r"(r) : "f"(hi_elem), "f"(lo_elem));
    return r;
}
// split adjacent pair (lo=a, hi=b) into bf16x2 hi and lo parts
__device__ __forceinline__ void split2(float a, float b, uint32_t& hi, uint32_t& lo) {
    hi = packbf(b, a);
    float ah = __uint_as_float(hi << 16);
    float bh = __uint_as_float(hi & 0xffff0000u);
    lo = packbf(b - bh, a - ah);
}
// m16n8k16 bf16 MMA, fp32 accumulate
__device__ __forceinline__ void mma16816(float* d, const uint32_t* a,
                                         uint32_t b0, uint32_t b1) {
    asm volatile(
        "mma.sync.aligned.m16n8k16.row.col.f32.bf16.bf16.f32 "
        "{%0,%1,%2,%3}, {%4,%5,%6,%7}, {%8,%9}, {%0,%1,%2,%3};"
        : "+f"(d[0]), "+f"(d[1]), "+f"(d[2]), "+f"(d[3])
        : "r"(a[0]), "r"(a[1]), "r"(a[2]), "r"(a[3]), "r"(b0), "r"(b1));
}

// ---------------------------------------------------------------------------
// Kernel 1: QKV GEMM on tensor cores (bf16x3 split), split-K, prefetched,
// wave-balanced, K-PERMUTED fragments:
// thread (t = lane&3) owns actual cols 4t..4t+3 <-> fragment k-positions
// {2t,2t+1,2t+8,2t+9} (global bijection; A and B permuted identically, sum
// unchanged).  A row fragment = ONE LDG.128 (was 2 LDG.64); B operand pair
// = ONE LDS.64 of adjacent words (was 2 scattered LDS.32).  Per k16: 4 LDG
// + 4 LDS + 8 split + 12 MMA (~60 issue slots, was ~76).
// ---------------------------------------------------------------------------
__global__ __launch_bounds__(128, 7) void qkv_gemm_kernel(
    const float* __restrict__ x,
    const float* __restrict__ wq,
    const float* __restrict__ wk,
    const float* __restrict__ wv)
{
    __shared__ __align__(16) uint32_t xhi[BATCH * XW];   // [n][k/2] bf16 pairs
    __shared__ __align__(16) uint32_t xlo[BATCH * XW];

    const int tid  = threadIdx.x;
    const int wid  = tid >> 5;
    const int lane = tid & 31;

    const int gn0 = blockIdx.x * ROWS_PB;
    const int mat = gn0 >> 12;
    const int n0  = gn0 & (IN_CHAN - 1);
    const int kb  = blockIdx.y * KS_LEN;
    const float* w = (mat == 0) ? wq : (mat == 1) ? wk : wv;

    // ---- stage x slice as bf16 hi/lo: 16 b x (KS_LEN/2=64) float2 ----
#pragma unroll
    for (int i = 0; i < 8; ++i) {
        int idx = tid + i * 128;        // [0,1024)
        int b   = idx >> 6;
        int kw  = idx & 63;
        float2 f = *(const float2*)(x + (size_t)b * IN_CHAN + kb + kw * 2);
        uint32_t h, l;
        split2(f.x, f.y, h, l);
        xhi[b * XW + kw] = h;
        xlo[b * XW + kw] = l;
    }
    __syncthreads();

    const int m0  = n0 + wid * 32;
    const int la4 = lane >> 2;
    const int t4  = (lane & 3) * 4;     // A col base (permuted)
    const int c0  = (lane & 3) * 2;     // D col base (output, unpermuted)

    const float* p0 = w + (size_t)(m0 + la4)      * IN_CHAN + kb + t4;
    const float* p1 = w + (size_t)(m0 + la4 + 8)  * IN_CHAN + kb + t4;
    const float* p2 = w + (size_t)(m0 + la4 + 16) * IN_CHAN + kb + t4;
    const float* p3 = w + (size_t)(m0 + la4 + 24) * IN_CHAN + kb + t4;

    float d[2][2][4];
#pragma unroll
    for (int t = 0; t < 2; ++t)
#pragma unroll
        for (int n = 0; n < 2; ++n)
#pragma unroll
            for (int j = 0; j < 4; ++j) d[t][n][j] = 0.f;

    const int brow0 = la4 * XW;         // n-tile 0 row base
    const int brow1 = (8 + la4) * XW;   // n-tile 1

    float4 pf[4];
#define PF_LOAD(kk)                                   \
    do {                                              \
        pf[0] = *(const float4*)(p0 + (kk));          \
        pf[1] = *(const float4*)(p1 + (kk));          \
        pf[2] = *(const float4*)(p2 + (kk));          \
        pf[3] = *(const float4*)(p3 + (kk));          \
    } while (0)

    PF_LOAD(0);

#pragma unroll
    for (int k = 0; k < KS_LEN; k += 16) {
        float4 cur[4];
#pragma unroll
        for (int i = 0; i < 4; ++i) cur[i] = pf[i];
        if (k + 16 < KS_LEN) PF_LOAD(k + 16);

        // A fragments: [r0 klo, r1 klo, r0 khi, r1 khi] per m-tile
        uint32_t ah[2][4], al[2][4];
        split2(cur[0].x, cur[0].y, ah[0][0], al[0][0]);
        split2(cur[1].x, cur[1].y, ah[0][1], al[0][1]);
        split2(cur[0].z, cur[0].w, ah[0][2], al[0][2]);
        split2(cur[1].z, cur[1].w, ah[0][3], al[0][3]);
        split2(cur[2].x, cur[2].y, ah[1][0], al[1][0]);
        split2(cur[3].x, cur[3].y, ah[1][1], al[1][1]);
        split2(cur[2].z, cur[2].w, ah[1][2], al[1][2]);
        split2(cur[3].z, cur[3].w, ah[1][3], al[1][3]);

        // B fragments: adjacent words (cols 4t..4t+3) -> one LDS.64 each
        const int kw = (k >> 1) + c0;   // even -> 8B aligned
        uint2 bh0 = *(const uint2*)&xhi[brow0 + kw];
        uint2 bl0 = *(const uint2*)&xlo[brow0 + kw];
        uint2 bh1 = *(const uint2*)&xhi[brow1 + kw];
        uint2 bl1 = *(const uint2*)&xlo[brow1 + kw];

#pragma unroll
        for (int t = 0; t < 2; ++t) {
            mma16816(d[t][0], ah[t], bh0.x, bh0.y);   // hi*hi
            mma16816(d[t][0], ah[t], bl0.x, bl0.y);   // hi*lo
            mma16816(d[t][0], al[t], bh0.x, bh0.y);   // lo*hi
            mma16816(d[t][1], ah[t], bh1.x, bh1.y);
            mma16816(d[t][1], ah[t], bl1.x, bl1.y);
            mma16816(d[t][1], al[t], bh1.x, bh1.y);
        }
    }
#undef PF_LOAD

    // epilogue (D layout unpermuted): rows la4 / la4+8 per m-tile
    const int p = blockIdx.y;
#pragma unroll
    for (int t = 0; t < 2; ++t) {
#pragma unroll
        for (int n = 0; n < 2; ++n) {
            int gnA = gn0 + wid * 32 + t * 16 + la4;
            int bcol = n * 8 + c0;
            float* dstA = g_part + ((size_t)p * NTOT + gnA) * BATCH + bcol;
            *(float2*)dstA = make_float2(d[t][n][0], d[t][n][1]);
            float* dstB = g_part + ((size_t)p * NTOT + gnA + 8) * BATCH + bcol;
            *(float2*)dstB = make_float2(d[t][n][2], d[t][n][3]);
        }
    }
}

// ---------------------------------------------------------------------------
// Kernel 2: coalesced split-K reduce + bias -> g_qkv[mat][b][n] (b-major).
// ---------------------------------------------------------------------------
__global__ __launch_bounds__(256) void reduce_bias_kernel(
    const float* __restrict__ bq,
    const float* __restrict__ bk,
    const float* __restrict__ bv)
{
    const int idx = blockIdx.x * 256 + threadIdx.x;   // [0, NTOT*BATCH)
    const int b   = idx & (BATCH - 1);
    const int gn  = idx >> 4;
    const int mat = gn >> 12;
    const int n   = gn & (IN_CHAN - 1);

    float s = 0.f;
#pragma unroll 8
    for (int p = 0; p < KSPLIT; ++p)
        s += g_part[(size_t)p * NTOT * BATCH + idx];

    const float* bias = (mat == 0) ? bq : (mat == 1) ? bk : bv;
    g_qkv[((size_t)mat * BATCH + b) * IN_CHAN + n] = s + bias[n];
}

// ---------------------------------------------------------------------------
// Kernel 3: nodes. Loads its k,v chunk from g_qkv (contiguous, L2), then
// evaluates F,G partials at 32 fixed Chebyshev nodes (domain +-QHALF).
// grid (16 batches, 16 chunks) x 512 thr.
// ---------------------------------------------------------------------------
__global__ __launch_bounds__(512) void attn_nodes_kernel()
{
    __shared__ float ks[CHLEN], vs[CHLEN];
    const int b   = blockIdx.x;
    const int ch  = blockIdx.y;
    const int tid = threadIdx.x;

    {
        int n   = tid & (CHLEN - 1);
        int sel = tid >> 8;             // 0 = k (mat 1), 1 = v (mat 2)
        float s = g_qkv[((size_t)(1 + sel) * BATCH + b) * IN_CHAN + ch * CHLEN + n];
        if (sel) vs[n] = s;
        else     ks[n] = s;
    }
    __syncthreads();

    const int node = tid >> 4;
    const int sub  = tid & 15;

    const float xt = QHALF * cosf(PI_F * (node + 0.5f) / NNODES);
    const float a  = xt * LOG2E;

    float aF = 0.f, aG = 0.f;
#pragma unroll
    for (int j = sub; j < CHLEN; j += 16) {
        float e = ex2(a * ks[j]);
        aG += e;
        aF = fmaf(e, vs[j], aF);
    }
#pragma unroll
    for (int o = 8; o; o >>= 1) {
        aF += __shfl_xor_sync(0xffffffffu, aF, o);
        aG += __shfl_xor_sync(0xffffffffu, aG, o);
    }
    if (sub == 0) {
        g_nodes[b][ch][0][node] = aF;
        g_nodes[b][ch][1][node] = aG;
    }
}

// ---------------------------------------------------------------------------
// Kernel 4: tiny fit. Sum node chunks + 32x32 DCT -> g_cheb[b][0..63].
// grid 16 x 64 thr (one block per batch; computed ONCE, not per eval block).
// ---------------------------------------------------------------------------
__global__ __launch_bounds__(64) void attn_fit_kernel()
{
    __shared__ float Fv[NNODES], Gv[NNODES], tab[128];
    const int b   = blockIdx.x;
    const int tid = threadIdx.x;

    {
        int node = tid & 31;
        int sel  = tid >> 5;
        float v = 0.f;
#pragma unroll
        for (int ch = 0; ch < NCHUNK; ++ch)
            v += g_nodes[b][ch][sel][node];
        if (sel == 0) Fv[node] = v;
        else          Gv[node] = v;
    }
    for (int u = tid; u < 128; u += 64)
        tab[u] = cosf((PI_F / 64.0f) * (float)u);
    __syncthreads();

    const int m = tid & 31;
    const float* src = (tid < 32) ? Fv : Gv;
    float c = 0.f;
#pragma unroll
    for (int t = 0; t < NNODES; ++t)
        c = fmaf(src[t], tab[(m * (2 * t + 1)) & 127], c);
    g_cheb[b][tid] = c * (2.0f / NNODES);
}

// ---------------------------------------------------------------------------
// Kernel 5: lean eval. Load 64 coeffs, read q, Clenshaw -> out.
// grid (16 x-chunks, 16 batches) x 256 thr.
// ---------------------------------------------------------------------------
__global__ __launch_bounds__(256) void attn_eval_kernel(float* __restrict__ out)
{
    __shared__ float cF[NNODES], cG[NNODES];
    const int b   = blockIdx.y;
    const int tid = threadIdx.x;

    if (tid < 64) {
        float c = g_cheb[b][tid];
        if (tid < 32) cF[tid] = c;
        else          cG[tid - 32] = c;
    }
    __syncthreads();

    const int i = blockIdx.x * 256 + tid;
    float q = g_qkv[(size_t)b * IN_CHAN + i];   // mat 0 = q

    float y = q * (1.0f / QHALF);
    y = fminf(1.f, fmaxf(-1.f, y));
    const float y2 = 2.f * y;

    float f1 = 0.f, f2 = 0.f, g1 = 0.f, g2 = 0.f;
#pragma unroll
    for (int m = NNODES - 1; m >= 1; --m) {
        float tf = fmaf(y2, f1, cF[m] - f2);
        f2 = f1; f1 = tf;
        float tg = fmaf(y2, g1, cG[m] - g2);
        g2 = g1; g1 = tg;
    }
    float F = fmaf(y, f1, 0.5f * cF[0]) - f2;
    float G = fmaf(y, g1, 0.5f * cG[0]) - g2;

    out[(size_t)b * IN_CHAN + i] = F / G;
}

// ---------------------------------------------------------------------------
extern "C" void kernel_launch(void* const* d_in, const int* in_sizes, int n_in,
                              void* d_out, int out_size)
{
    (void)in_sizes; (void)n_in; (void)out_size;
    const float* x  = (const float*)d_in[0];
    const float* wq = (const float*)d_in[1];
    const float* bq = (const float*)d_in[2];
    const float* wk = (const float*)d_in[3];
    const float* bk = (const float*)d_in[4];
    const float* wv = (const float*)d_in[5];
    const float* bv = (const float*)d_in[6];
    float* out = (float*)d_out;

    qkv_gemm_kernel<<<dim3(NTOT / ROWS_PB, KSPLIT), 128>>>(x, wq, wk, wv);
    reduce_bias_kernel<<<(NTOT * BATCH) / 256, 256>>>(bq, bk, bv);
    attn_nodes_kernel<<<dim3(BATCH, NCHUNK), 512>>>();
    attn_fit_kernel<<<BATCH, 64>>>();
    attn_eval_kernel<<<dim3(IN_CHAN / 256, BATCH), 256>>>(out);
}

// round 15
// speedup vs baseline: 1.2463x; 1.0776x over previous
#include <cuda_runtime.h>
#include <cstdint>

#define IN_CHAN 4096
#define BATCH   16
#define NTOT    (3 * IN_CHAN)          // 12288 stacked W rows (q,k,v)
#define KSPLIT  16
#define KS_LEN  (IN_CHAN / KSPLIT)     // 256 k per block
#define ROWS_PB 64                     // W rows per block (4 warps x 16)
#define NNODES  32
#define NCHUNK  16
#define CHLEN   (IN_CHAN / NCHUNK)     // 256
#define QHALF   4.0f
#define LOG2E   1.4426950408889634f
#define PI_F    3.14159265358979323846f

#define XW      132                    // x smem row pitch in b32 words (even)

// Scratch (device globals; no allocation allowed anywhere)
__device__ float g_part[KSPLIT * NTOT * BATCH];       // split-K partials (12.6MB)
__device__ float g_qkv[3 * BATCH * IN_CHAN];          // reduced q,k,v (b-major)
__device__ float g_nodes[BATCH][NCHUNK][2][NNODES];   // per j-chunk partial F,G

__device__ __forceinline__ float ex2(float x) {
    float r;
    asm("ex2.approx.ftz.f32 %0, %1;" : "=f"(r) : "f"(x));
    return r;
}
__device__ __forceinline__ uint32_t packbf(float hi_elem, float lo_elem) {
    uint32_t r;
    asm("cvt.rn.bf16x2.f32 %0, %1, %2;" : "=r"(r) : "f"(hi_elem), "f"(lo_elem));
    return r;
}
// split adjacent pair (lo=a, hi=b) into bf16x2 hi and lo parts
__device__ __forceinline__ void split2(float a, float b, uint32_t& hi, uint32_t& lo) {
    hi = packbf(b, a);
    float ah = __uint_as_float(hi << 16);
    float bh = __uint_as_float(hi & 0xffff0000u);
    lo = packbf(b - bh, a - ah);
}
// m16n8k16 bf16 MMA, fp32 accumulate
__device__ __forceinline__ void mma16816(float* d, const uint32_t* a,
                                         uint32_t b0, uint32_t b1) {
    asm volatile(
        "mma.sync.aligned.m16n8k16.row.col.f32.bf16.bf16.f32 "
        "{%0,%1,%2,%3}, {%4,%5,%6,%7}, {%8,%9}, {%0,%1,%2,%3};"
        : "+f"(d[0]), "+f"(d[1]), "+f"(d[2]), "+f"(d[3])
        : "r"(a[0]), "r"(a[1]), "r"(a[2]), "r"(a[3]), "r"(b0), "r"(b1));
}

// ---------------------------------------------------------------------------
// Kernel 1: QKV GEMM on tensor cores (bf16x3 split), split-K, prefetched,
// wave-balanced, k-permuted fragments, REDUCED PARTIAL TRAFFIC:
// KSPLIT=16 x ROWS_PB=64 keeps grid at 3072 (2.97 waves, eff 0.99) while
// halving g_part writes (25MB -> 12.6MB).  Warp = one m-tile (16 rows) x
// 16 batches x 256 k.  Per k16 per warp: 2 LDG.128 (k-permuted A rows,
// prefetched 1 step) + 4 LDS.64 (B pairs) + 4 splits + 6 MMA.
// ---------------------------------------------------------------------------
__global__ __launch_bounds__(128, 7) void qkv_gemm_kernel(
    const float* __restrict__ x,
    const float* __restrict__ wq,
    const float* __restrict__ wk,
    const float* __restrict__ wv)
{
    __shared__ __align__(16) uint32_t xhi[BATCH * XW];   // [n][k/2] bf16 pairs
    __shared__ __align__(16) uint32_t xlo[BATCH * XW];

    const int tid  = threadIdx.x;
    const int wid  = tid >> 5;
    const int lane = tid & 31;

    const int gn0 = blockIdx.x * ROWS_PB;
    const int mat = gn0 >> 12;
    const int n0  = gn0 & (IN_CHAN - 1);
    const int kb  = blockIdx.y * KS_LEN;
    const float* w = (mat == 0) ? wq : (mat == 1) ? wk : wv;

    // ---- stage x slice as bf16 hi/lo: 16 b x (KS_LEN/2=128) float2 ----
#pragma unroll
    for (int i = 0; i < 16; ++i) {
        int idx = tid + i * 128;        // [0,2048)
        int b   = idx >> 7;
        int kw  = idx & 127;
        float2 f = *(const float2*)(x + (size_t)b * IN_CHAN + kb + kw * 2);
        uint32_t h, l;
        split2(f.x, f.y, h, l);
        xhi[b * XW + kw] = h;
        xlo[b * XW + kw] = l;
    }
    __syncthreads();

    const int m0  = n0 + wid * 16;      // warp's m-tile base row
    const int la4 = lane >> 2;
    const int t4  = (lane & 3) * 4;     // A col base (k-permuted)
    const int c0  = (lane & 3) * 2;     // D col base (output)

    const float* p0 = w + (size_t)(m0 + la4)     * IN_CHAN + kb + t4;
    const float* p1 = w + (size_t)(m0 + la4 + 8) * IN_CHAN + kb + t4;

    float d[2][4];                      // [n-tile][frag]
#pragma unroll
    for (int n = 0; n < 2; ++n)
#pragma unroll
        for (int j = 0; j < 4; ++j) d[n][j] = 0.f;

    const int brow0 = la4 * XW;         // n-tile 0 row base
    const int brow1 = (8 + la4) * XW;   // n-tile 1

    float4 pf0 = *(const float4*)p0;
    float4 pf1 = *(const float4*)p1;

#pragma unroll 4
    for (int k = 0; k < KS_LEN; k += 16) {
        float4 cur0 = pf0, cur1 = pf1;
        if (k + 16 < KS_LEN) {
            pf0 = *(const float4*)(p0 + k + 16);
            pf1 = *(const float4*)(p1 + k + 16);
        }

        uint32_t ah[4], al[4];
        split2(cur0.x, cur0.y, ah[0], al[0]);   // row la4,  klo
        split2(cur1.x, cur1.y, ah[1], al[1]);   // row la4+8, klo
        split2(cur0.z, cur0.w, ah[2], al[2]);   // row la4,  khi
        split2(cur1.z, cur1.w, ah[3], al[3]);   // row la4+8, khi

        const int kw = (k >> 1) + c0;           // even -> 8B aligned
        uint2 bh0 = *(const uint2*)&xhi[brow0 + kw];
        uint2 bl0 = *(const uint2*)&xlo[brow0 + kw];
        uint2 bh1 = *(const uint2*)&xhi[brow1 + kw];
        uint2 bl1 = *(const uint2*)&xlo[brow1 + kw];

        mma16816(d[0], ah, bh0.x, bh0.y);       // hi*hi
        mma16816(d[0], ah, bl0.x, bl0.y);       // hi*lo
        mma16816(d[0], al, bh0.x, bh0.y);       // lo*hi
        mma16816(d[1], ah, bh1.x, bh1.y);
        mma16816(d[1], ah, bl1.x, bl1.y);
        mma16816(d[1], al, bh1.x, bh1.y);
    }

    // epilogue: rows m-tile la4 / la4+8
    const int p = blockIdx.y;
#pragma unroll
    for (int n = 0; n < 2; ++n) {
        int gnA  = gn0 + wid * 16 + la4;
        int bcol = n * 8 + c0;
        float* dstA = g_part + ((size_t)p * NTOT + gnA) * BATCH + bcol;
        *(float2*)dstA = make_float2(d[n][0], d[n][1]);
        float* dstB = g_part + ((size_t)p * NTOT + gnA + 8) * BATCH + bcol;
        *(float2*)dstB = make_float2(d[n][2], d[n][3]);
    }
}

// ---------------------------------------------------------------------------
// Kernel 2: coalesced split-K reduce + bias -> g_qkv[mat][b][n] (b-major).
// ---------------------------------------------------------------------------
__global__ __launch_bounds__(256) void reduce_bias_kernel(
    const float* __restrict__ bq,
    const float* __restrict__ bk,
    const float* __restrict__ bv)
{
    const int idx = blockIdx.x * 256 + threadIdx.x;   // [0, NTOT*BATCH)
    const int b   = idx & (BATCH - 1);
    const int gn  = idx >> 4;
    const int mat = gn >> 12;
    const int n   = gn & (IN_CHAN - 1);

    float s = 0.f;
#pragma unroll
    for (int p = 0; p < KSPLIT; ++p)
        s += g_part[(size_t)p * NTOT * BATCH + idx];

    const float* bias = (mat == 0) ? bq : (mat == 1) ? bk : bv;
    g_qkv[((size_t)mat * BATCH + b) * IN_CHAN + n] = s + bias[n];
}

// ---------------------------------------------------------------------------
// Kernel 3: nodes. Loads its k,v chunk from g_qkv (contiguous, L2), then
// evaluates F,G partials at 32 fixed Chebyshev nodes (domain +-QHALF).
// grid (16 batches, 16 chunks) x 512 thr.
// ---------------------------------------------------------------------------
__global__ __launch_bounds__(512) void attn_nodes_kernel()
{
    __shared__ float ks[CHLEN], vs[CHLEN];
    const int b   = blockIdx.x;
    const int ch  = blockIdx.y;
    const int tid = threadIdx.x;

    {
        int n   = tid & (CHLEN - 1);
        int sel = tid >> 8;             // 0 = k (mat 1), 1 = v (mat 2)
        float s = g_qkv[((size_t)(1 + sel) * BATCH + b) * IN_CHAN + ch * CHLEN + n];
        if (sel) vs[n] = s;
        else     ks[n] = s;
    }
    __syncthreads();

    const int node = tid >> 4;
    const int sub  = tid & 15;

    const float xt = QHALF * __cosf(PI_F * (node + 0.5f) / NNODES);
    const float a  = xt * LOG2E;

    float aF = 0.f, aG = 0.f;
#pragma unroll
    for (int j = sub; j < CHLEN; j += 16) {
        float e = ex2(a * ks[j]);
        aG += e;
        aF = fmaf(e, vs[j], aF);
    }
#pragma unroll
    for (int o = 8; o; o >>= 1) {
        aF += __shfl_xor_sync(0xffffffffu, aF, o);
        aG += __shfl_xor_sync(0xffffffffu, aG, o);
    }
    if (sub == 0) {
        g_nodes[b][ch][0][node] = aF;
        g_nodes[b][ch][1][node] = aG;
    }
}

// ---------------------------------------------------------------------------
// Kernel 4: fused fit + eval (no separate fit launch). Each block: sum the
// 16 node chunks, 32x32 DCT via __cosf (MUFU, cheap), then Clenshaw per
// output.  grid (16 x-chunks, 16 batches) x 256 thr.
// ---------------------------------------------------------------------------
__global__ __launch_bounds__(256) void attn_eval_kernel(float* __restrict__ out)
{
    __shared__ float Fv[NNODES], Gv[NNODES], cF[NNODES], cG[NNODES];
    const int b   = blockIdx.y;
    const int tid = threadIdx.x;

    if (tid < 64) {
        int node = tid & 31;
        int sel  = tid >> 5;
        float v = 0.f;
#pragma unroll
        for (int ch = 0; ch < NCHUNK; ++ch)
            v += g_nodes[b][ch][sel][node];
        if (sel == 0) Fv[node] = v;
        else          Gv[node] = v;
    }
    __syncthreads();

    if (tid < 64) {
        int m = tid & 31;
        const float* src = (tid < 32) ? Fv : Gv;
        float c = 0.f;
#pragma unroll
        for (int t = 0; t < NNODES; ++t) {
            int u = (m * (2 * t + 1)) & 127;
            c = fmaf(src[t], __cosf((PI_F / 64.0f) * (float)u), c);
        }
        c *= 2.0f / NNODES;
        if (tid < 32) cF[m] = c;
        else          cG[m] = c;
    }
    __syncthreads();

    const int i = blockIdx.x * 256 + tid;
    float q = g_qkv[(size_t)b * IN_CHAN + i];   // mat 0 = q

    float y = q * (1.0f / QHALF);
    y = fminf(1.f, fmaxf(-1.f, y));
    const float y2 = 2.f * y;

    float f1 = 0.f, f2 = 0.f, g1 = 0.f, g2 = 0.f;
#pragma unroll
    for (int m = NNODES - 1; m >= 1; --m) {
        float tf = fmaf(y2, f1, cF[m] - f2);
        f2 = f1; f1 = tf;
        float tg = fmaf(y2, g1, cG[m] - g2);
        g2 = g1; g1 = tg;
    }
    float F = fmaf(y, f1, 0.5f * cF[0]) - f2;
    float G = fmaf(y, g1, 0.5f * cG[0]) - g2;

    out[(size_t)b * IN_CHAN + i] = F / G;
}

// ---------------------------------------------------------------------------
extern "C" void kernel_launch(void* const* d_in, const int* in_sizes, int n_in,
                              void* d_out, int out_size)
{
    (void)in_sizes; (void)n_in; (void)out_size;
    const float* x  = (const float*)d_in[0];
    const float* wq = (const float*)d_in[1];
    const float* bq = (const float*)d_in[2];
    const float* wk = (const float*)d_in[3];
    const float* bk = (const float*)d_in[4];
    const float* wv = (const float*)d_in[5];
    const float* bv = (const float*)d_in[6];
    float* out = (float*)d_out;

    qkv_gemm_kernel<<<dim3(NTOT / ROWS_PB, KSPLIT), 128>>>(x, wq, wk, wv);
    reduce_bias_kernel<<<(NTOT * BATCH) / 256, 256>>>(bq, bk, bv);
    attn_nodes_kernel<<<dim3(BATCH, NCHUNK), 512>>>();
    attn_eval_kernel<<<dim3(IN_CHAN / 256, BATCH), 256>>>(out);
}

// round 16
// speedup vs baseline: 1.2471x; 1.0006x over previous
#include <cuda_runtime.h>
#include <cstdint>

#define IN_CHAN 4096
#define BATCH   16
#define NTOT    (3 * IN_CHAN)          // 12288 stacked W rows (q,k,v)
#define KSPLIT  16
#define KS_LEN  (IN_CHAN / KSPLIT)     // 256 k per block
#define ROWS_PB 64                     // W rows per block (4 warps x 16)
#define NNODES  32
#define NCHUNK  16
#define CHLEN   (IN_CHAN / NCHUNK)     // 256
#define QHALF   4.0f
#define LOG2E   1.4426950408889634f
#define PI_F    3.14159265358979323846f

#define XW      132                    // x smem row pitch in b32 words (even)

// Scratch (device globals; no allocation allowed anywhere)
__device__ float g_part[KSPLIT * NTOT * BATCH];       // split-K partials (12.6MB)
__device__ float g_qkv[3 * BATCH * IN_CHAN];          // reduced q,k,v (b-major)
__device__ float g_nodes[BATCH][NCHUNK][2][NNODES];   // per j-chunk partial F,G

__device__ __forceinline__ float ex2(float x) {
    float r;
    asm("ex2.approx.ftz.f32 %0, %1;" : "=f"(r) : "f"(x));
    return r;
}
__device__ __forceinline__ uint32_t packbf(float hi_elem, float lo_elem) {
    uint32_t r;
    asm("cvt.rn.bf16x2.f32 %0, %1, %2;" : "=r"(r) : "f"(hi_elem), "f"(lo_elem));
    return r;
}
// split adjacent pair (lo=a, hi=b) into bf16x2 hi and lo parts
__device__ __forceinline__ void split2(float a, float b, uint32_t& hi, uint32_t& lo) {
    hi = packbf(b, a);
    float ah = __uint_as_float(hi << 16);
    float bh = __uint_as_float(hi & 0xffff0000u);
    lo = packbf(b - bh, a - ah);
}
// m16n8k16 bf16 MMA, fp32 accumulate
__device__ __forceinline__ void mma16816(float* d, const uint32_t* a,
                                         uint32_t b0, uint32_t b1) {
    asm volatile(
        "mma.sync.aligned.m16n8k16.row.col.f32.bf16.bf16.f32 "
        "{%0,%1,%2,%3}, {%4,%5,%6,%7}, {%8,%9}, {%0,%1,%2,%3};"
        : "+f"(d[0]), "+f"(d[1]), "+f"(d[2]), "+f"(d[3])
        : "r"(a[0]), "r"(a[1]), "r"(a[2]), "r"(a[3]), "r"(b0), "r"(b1));
}

// ---------------------------------------------------------------------------
// Kernel 1: QKV GEMM on tensor cores (bf16x3 split), split-K, wave-balanced,
// k-permuted fragments, PREFETCH DEPTH 2 (4 LDG.128 in flight per thread ->
// 2KB/warp, 56KB/SM in flight vs ~17KB needed to cover DRAM latency).
// Warp = one m-tile (16 rows) x 16 batches x 256 k.
// Per k16 per warp: 2 LDG.128 + 4 LDS.64 + 4 splits + 6 MMA.
// ---------------------------------------------------------------------------
__global__ __launch_bounds__(128, 7) void qkv_gemm_kernel(
    const float* __restrict__ x,
    const float* __restrict__ wq,
    const float* __restrict__ wk,
    const float* __restrict__ wv)
{
    __shared__ __align__(16) uint32_t xhi[BATCH * XW];   // [n][k/2] bf16 pairs
    __shared__ __align__(16) uint32_t xlo[BATCH * XW];

    const int tid  = threadIdx.x;
    const int wid  = tid >> 5;
    const int lane = tid & 31;

    const int gn0 = blockIdx.x * ROWS_PB;
    const int mat = gn0 >> 12;
    const int n0  = gn0 & (IN_CHAN - 1);
    const int kb  = blockIdx.y * KS_LEN;
    const float* w = (mat == 0) ? wq : (mat == 1) ? wk : wv;

    // ---- stage x slice as bf16 hi/lo: 16 b x (KS_LEN/2=128) float2 ----
#pragma unroll
    for (int i = 0; i < 16; ++i) {
        int idx = tid + i * 128;        // [0,2048)
        int b   = idx >> 7;
        int kw  = idx & 127;
        float2 f = *(const float2*)(x + (size_t)b * IN_CHAN + kb + kw * 2);
        uint32_t h, l;
        split2(f.x, f.y, h, l);
        xhi[b * XW + kw] = h;
        xlo[b * XW + kw] = l;
    }
    __syncthreads();

    const int m0  = n0 + wid * 16;      // warp's m-tile base row
    const int la4 = lane >> 2;
    const int t4  = (lane & 3) * 4;     // A col base (k-permuted)
    const int c0  = (lane & 3) * 2;     // D col base (output)

    const float* p0 = w + (size_t)(m0 + la4)     * IN_CHAN + kb + t4;
    const float* p1 = w + (size_t)(m0 + la4 + 8) * IN_CHAN + kb + t4;

    float d[2][4];                      // [n-tile][frag]
#pragma unroll
    for (int n = 0; n < 2; ++n)
#pragma unroll
        for (int j = 0; j < 4; ++j) d[n][j] = 0.f;

    const int brow0 = la4 * XW;         // n-tile 0 row base
    const int brow1 = (8 + la4) * XW;   // n-tile 1

    // prefetch depth 2
    float4 pfA0 = *(const float4*)p0;
    float4 pfA1 = *(const float4*)p1;
    float4 pfB0 = *(const float4*)(p0 + 16);
    float4 pfB1 = *(const float4*)(p1 + 16);

#pragma unroll 4
    for (int k = 0; k < KS_LEN; k += 16) {
        float4 cur0 = pfA0, cur1 = pfA1;
        pfA0 = pfB0;
        pfA1 = pfB1;
        if (k + 32 < KS_LEN) {
            pfB0 = *(const float4*)(p0 + k + 32);
            pfB1 = *(const float4*)(p1 + k + 32);
        }

        uint32_t ah[4], al[4];
        split2(cur0.x, cur0.y, ah[0], al[0]);   // row la4,  klo
        split2(cur1.x, cur1.y, ah[1], al[1]);   // row la4+8, klo
        split2(cur0.z, cur0.w, ah[2], al[2]);   // row la4,  khi
        split2(cur1.z, cur1.w, ah[3], al[3]);   // row la4+8, khi

        const int kw = (k >> 1) + c0;           // even -> 8B aligned
        uint2 bh0 = *(const uint2*)&xhi[brow0 + kw];
        uint2 bl0 = *(const uint2*)&xlo[brow0 + kw];
        uint2 bh1 = *(const uint2*)&xhi[brow1 + kw];
        uint2 bl1 = *(const uint2*)&xlo[brow1 + kw];

        mma16816(d[0], ah, bh0.x, bh0.y);       // hi*hi
        mma16816(d[0], ah, bl0.x, bl0.y);       // hi*lo
        mma16816(d[0], al, bh0.x, bh0.y);       // lo*hi
        mma16816(d[1], ah, bh1.x, bh1.y);
        mma16816(d[1], ah, bl1.x, bl1.y);
        mma16816(d[1], al, bh1.x, bh1.y);
    }

    // epilogue: rows m-tile la4 / la4+8
    const int p = blockIdx.y;
#pragma unroll
    for (int n = 0; n < 2; ++n) {
        int gnA  = gn0 + wid * 16 + la4;
        int bcol = n * 8 + c0;
        float* dstA = g_part + ((size_t)p * NTOT + gnA) * BATCH + bcol;
        *(float2*)dstA = make_float2(d[n][0], d[n][1]);
        float* dstB = g_part + ((size_t)p * NTOT + gnA + 8) * BATCH + bcol;
        *(float2*)dstB = make_float2(d[n][2], d[n][3]);
    }
}

// ---------------------------------------------------------------------------
// Kernel 2: coalesced split-K reduce + bias -> g_qkv[mat][b][n] (b-major).
// ---------------------------------------------------------------------------
__global__ __launch_bounds__(256) void reduce_bias_kernel(
    const float* __restrict__ bq,
    const float* __restrict__ bk,
    const float* __restrict__ bv)
{
    const int idx = blockIdx.x * 256 + threadIdx.x;   // [0, NTOT*BATCH)
    const int b   = idx & (BATCH - 1);
    const int gn  = idx >> 4;
    const int mat = gn >> 12;
    const int n   = gn & (IN_CHAN - 1);

    float s = 0.f;
#pragma unroll
    for (int p = 0; p < KSPLIT; ++p)
        s += g_part[(size_t)p * NTOT * BATCH + idx];

    const float* bias = (mat == 0) ? bq : (mat == 1) ? bk : bv;
    g_qkv[((size_t)mat * BATCH + b) * IN_CHAN + n] = s + bias[n];
}

// ---------------------------------------------------------------------------
// Kernel 3: nodes. Loads its k,v chunk from g_qkv (contiguous, L2), then
// evaluates F,G partials at 32 fixed Chebyshev nodes (domain +-QHALF).
// grid (16 batches, 16 chunks) x 512 thr.
// ---------------------------------------------------------------------------
__global__ __launch_bounds__(512) void attn_nodes_kernel()
{
    __shared__ float ks[CHLEN], vs[CHLEN];
    const int b   = blockIdx.x;
    const int ch  = blockIdx.y;
    const int tid = threadIdx.x;

    {
        int n   = tid & (CHLEN - 1);
        int sel = tid >> 8;             // 0 = k (mat 1), 1 = v (mat 2)
        float s = g_qkv[((size_t)(1 + sel) * BATCH + b) * IN_CHAN + ch * CHLEN + n];
        if (sel) vs[n] = s;
        else     ks[n] = s;
    }
    __syncthreads();

    const int node = tid >> 4;
    const int sub  = tid & 15;

    const float xt = QHALF * __cosf(PI_F * (node + 0.5f) / NNODES);
    const float a  = xt * LOG2E;

    float aF = 0.f, aG = 0.f;
#pragma unroll
    for (int j = sub; j < CHLEN; j += 16) {
        float e = ex2(a * ks[j]);
        aG += e;
        aF = fmaf(e, vs[j], aF);
    }
#pragma unroll
    for (int o = 8; o; o >>= 1) {
        aF += __shfl_xor_sync(0xffffffffu, aF, o);
        aG += __shfl_xor_sync(0xffffffffu, aG, o);
    }
    if (sub == 0) {
        g_nodes[b][ch][0][node] = aF;
        g_nodes[b][ch][1][node] = aG;
    }
}

// ---------------------------------------------------------------------------
// Kernel 4: fused fit + eval, amortized. 512-thr blocks, grid (8, 16) =
// 128 blocks (prologue runs 2x fewer times over 2x more outputs -> 4x
// amortization). Prologue: chunk-sum + 32x32 DCT via __cosf. Then Clenshaw.
// ---------------------------------------------------------------------------
__global__ __launch_bounds__(512) void attn_eval_kernel(float* __restrict__ out)
{
    __shared__ float Fv[NNODES], Gv[NNODES], cF[NNODES], cG[NNODES];
    const int b   = blockIdx.y;
    const int tid = threadIdx.x;

    if (tid < 64) {
        int node = tid & 31;
        int sel  = tid >> 5;
        float v = 0.f;
#pragma unroll
        for (int ch = 0; ch < NCHUNK; ++ch)
            v += g_nodes[b][ch][sel][node];
        if (sel == 0) Fv[node] = v;
        else          Gv[node] = v;
    }
    __syncthreads();

    if (tid < 64) {
        int m = tid & 31;
        const float* src = (tid < 32) ? Fv : Gv;
        float c = 0.f;
#pragma unroll
        for (int t = 0; t < NNODES; ++t) {
            int u = (m * (2 * t + 1)) & 127;
            c = fmaf(src[t], __cosf((PI_F / 64.0f) * (float)u), c);
        }
        c *= 2.0f / NNODES;
        if (tid < 32) cF[m] = c;
        else          cG[m] = c;
    }
    __syncthreads();

    const int i = blockIdx.x * 512 + tid;
    float q = g_qkv[(size_t)b * IN_CHAN + i];   // mat 0 = q

    float y = q * (1.0f / QHALF);
    y = fminf(1.f, fmaxf(-1.f, y));
    const float y2 = 2.f * y;

    float f1 = 0.f, f2 = 0.f, g1 = 0.f, g2 = 0.f;
#pragma unroll
    for (int m = NNODES - 1; m >= 1; --m) {
        float tf = fmaf(y2, f1, cF[m] - f2);
        f2 = f1; f1 = tf;
        float tg = fmaf(y2, g1, cG[m] - g2);
        g2 = g1; g1 = tg;
    }
    float F = fmaf(y, f1, 0.5f * cF[0]) - f2;
    float G = fmaf(y, g1, 0.5f * cG[0]) - g2;

    out[(size_t)b * IN_CHAN + i] = F / G;
}

// ---------------------------------------------------------------------------
extern "C" void kernel_launch(void* const* d_in, const int* in_sizes, int n_in,
                              void* d_out, int out_size)
{
    (void)in_sizes; (void)n_in; (void)out_size;
    const float* x  = (const float*)d_in[0];
    const float* wq = (const float*)d_in[1];
    const float* bq = (const float*)d_in[2];
    const float* wk = (const float*)d_in[3];
    const float* bk = (const float*)d_in[4];
    const float* wv = (const float*)d_in[5];
    const float* bv = (const float*)d_in[6];
    float* out = (float*)d_out;

    qkv_gemm_kernel<<<dim3(NTOT / ROWS_PB, KSPLIT), 128>>>(x, wq, wk, wv);
    reduce_bias_kernel<<<(NTOT * BATCH) / 256, 256>>>(bq, bk, bv);
    attn_nodes_kernel<<<dim3(BATCH, NCHUNK), 512>>>();
    attn_eval_kernel<<<dim3(IN_CHAN / 512, BATCH), 512>>>(out);
}